// round 2
// baseline (speedup 1.0000x reference)
#include <cuda_runtime.h>

// Problem constants (fixed shapes)
#define B_    4
#define N_    16384
#define KNN   16
#define CIN   64
#define CP    68            // padded channels per row: [features 0..63, xyz 64..66, pad 67]
#define W16   16
#define JTOT  (W16 * CP)    // 1088
#define COUT  128
#define MT    32            // points per block in main kernel
#define AGG_STRIDE 1092     // smem row stride (multiple of 4; %32 == 4 -> conflict-free phase 3)
#define NEG_SLOPE 0.1f

// Scratch (static device globals; no runtime allocation)
__device__ __align__(16) float g_feats[B_ * N_ * CP];     // ~17.8 MB channel-last padded features
__device__ __align__(16) float g_linw[COUT * JTOT];       // ~557 KB re-laid-out lin_w

__device__ __forceinline__ float leaky(float x) { return x >= 0.f ? x : NEG_SLOPE * x; }

// ---------------------------------------------------------------------------
// Kernel 0a: repack lin_w [128, 16*67] -> [128, 16*68] with channel reorder
// reference flat index: j = w*67 + c_ref, c_ref in order [xyz(0..2), features(3..66)]
// our layout:           j' = w*68 + c,    c in order [features(0..63), xyz(64..66), pad(67)=0]
// ---------------------------------------------------------------------------
__global__ void pack_linw(const float* __restrict__ lin_w) {
    int idx = blockIdx.x * blockDim.x + threadIdx.x;
    if (idx >= COUT * JTOT) return;
    int o = idx / JTOT;
    int jj = idx % JTOT;
    int w = jj / CP;
    int c = jj % CP;
    float v = 0.f;
    if (c < 64)       v = lin_w[o * 1072 + w * 67 + (c + 3)];   // feature channel c -> ref idx c+3
    else if (c < 67)  v = lin_w[o * 1072 + w * 67 + (c - 64)];  // xyz channel -> ref idx 0..2
    g_linw[o * JTOT + jj] = v;
}

// ---------------------------------------------------------------------------
// Kernel 0b: build channel-last padded feats rows g_feats[(b*N + n)*68 + c]
// ---------------------------------------------------------------------------
__global__ void pack_feats(const float* __restrict__ xyz, const float* __restrict__ feat) {
    int n = blockIdx.x * blockDim.x + threadIdx.x;
    int bc = blockIdx.y;              // b*CP + c
    int b = bc / CP;
    int c = bc % CP;
    if (n >= N_) return;
    float v = 0.f;
    if (c < 64)       v = feat[(b * CIN + c) * N_ + n];
    else if (c < 67)  v = xyz[(b * 3 + (c - 64)) * N_ + n];
    g_feats[(b * N_ + n) * CP + c] = v;
}

// ---------------------------------------------------------------------------
// Main fused kernel: one block = 32 points.
// Phase 1: weight MLP -> wk_s[m][k][16]
// Phase 2: agg[m][w*68+c] into smem (features via reg accumulators, xyz part separately)
// Phase 3: out[m][o] = leaky(sum_j agg[m][j]*linw[o][j] + lin_b[o])
// ---------------------------------------------------------------------------
extern __shared__ float s_mem[];

__global__ __launch_bounds__(256, 1)
void pointconv_main(const float* __restrict__ xyz, const int* __restrict__ knn,
                    const float* __restrict__ w1, const float* __restrict__ b1,
                    const float* __restrict__ w2, const float* __restrict__ b2,
                    const float* __restrict__ lin_b, float* __restrict__ out)
{
    float* agg_s = s_mem;                              // MT * AGG_STRIDE floats
    float* wk_s  = agg_s + MT * AGG_STRIDE;            // MT * KNN * 16 floats
    int*   gid_s = (int*)(wk_s + MT * KNN * 16);       // MT * KNN ints

    const int tid = threadIdx.x;
    const int p0  = blockIdx.x * MT;
    const int b   = p0 / N_;
    const int n0  = p0 % N_;

    // ---------------- Phase 1: neighbor-offset MLP (2 (m,k) pairs per thread) --------
    {
        const int m  = tid >> 3;               // 0..31
        const int k2 = (tid & 7) << 1;         // 0,2,...,14
        const int n  = n0 + m;
        const float cx0 = xyz[(b * 3 + 0) * N_ + n];
        const float cx1 = xyz[(b * 3 + 1) * N_ + n];
        const float cx2 = xyz[(b * 3 + 2) * N_ + n];
        #pragma unroll
        for (int kk = 0; kk < 2; kk++) {
            const int k = k2 + kk;
            const int idx = knn[(b * N_ + n) * KNN + k];
            gid_s[m * KNN + k] = (b * N_ + idx) * CP;
            const float d0 = xyz[(b * 3 + 0) * N_ + idx] - cx0;
            const float d1 = xyz[(b * 3 + 1) * N_ + idx] - cx1;
            const float d2 = xyz[(b * 3 + 2) * N_ + idx] - cx2;
            float h[8];
            #pragma unroll
            for (int o = 0; o < 8; o++) {
                float s = fmaf(w1[o * 3 + 0], d0,
                          fmaf(w1[o * 3 + 1], d1,
                          fmaf(w1[o * 3 + 2], d2, b1[o])));
                h[o] = leaky(s);
            }
            #pragma unroll
            for (int o = 0; o < 16; o++) {
                float s = b2[o];
                #pragma unroll
                for (int hh = 0; hh < 8; hh++) s = fmaf(w2[o * 8 + hh], h[hh], s);
                wk_s[(m * KNN + k) * 16 + o] = leaky(s);
            }
        }
    }
    __syncthreads();

    // ---------------- Phase 2: agg accumulation --------------------------------------
    {
        const int m  = tid >> 3;               // 0..31 (point)
        const int cb = (tid & 7) << 3;         // feature-channel base, 0..56 step 8
        const int*   gidx = &gid_s[m * KNN];
        const float* wkm  = &wk_s[m * KNN * 16];

        // features part (c = 0..63), two halves of w (8 each) to bound registers
        #pragma unroll
        for (int wp = 0; wp < 2; wp++) {
            float acc[8][8];
            #pragma unroll
            for (int w = 0; w < 8; w++)
                #pragma unroll
                for (int c = 0; c < 8; c++) acc[w][c] = 0.f;

            #pragma unroll
            for (int k = 0; k < KNN; k++) {
                const float* f = &g_feats[gidx[k] + cb];
                const float4 fa = *(const float4*)f;
                const float4 fb = *(const float4*)(f + 4);
                const float4 wv0 = *(const float4*)&wkm[k * 16 + wp * 8];
                const float4 wv1 = *(const float4*)&wkm[k * 16 + wp * 8 + 4];
                const float wv[8] = {wv0.x, wv0.y, wv0.z, wv0.w, wv1.x, wv1.y, wv1.z, wv1.w};
                const float fv[8] = {fa.x, fa.y, fa.z, fa.w, fb.x, fb.y, fb.z, fb.w};
                #pragma unroll
                for (int w = 0; w < 8; w++)
                    #pragma unroll
                    for (int c = 0; c < 8; c++)
                        acc[w][c] = fmaf(wv[w], fv[c], acc[w][c]);
            }
            #pragma unroll
            for (int w = 0; w < 8; w++) {
                float* dst = &agg_s[m * AGG_STRIDE + (wp * 8 + w) * CP + cb];
                *(float4*)dst       = make_float4(acc[w][0], acc[w][1], acc[w][2], acc[w][3]);
                *(float4*)(dst + 4) = make_float4(acc[w][4], acc[w][5], acc[w][6], acc[w][7]);
            }
        }

        // xyz part (c = 64..66, pad 67=0); each thread handles 2 w's
        const int wq = (tid & 7) << 1;
        float s00 = 0.f, s01 = 0.f, s02 = 0.f;
        float s10 = 0.f, s11 = 0.f, s12 = 0.f;
        #pragma unroll
        for (int k = 0; k < KNN; k++) {
            const int g = gidx[k];
            const float4 fx = *(const float4*)&g_feats[g + 64];   // x, y, z, 0
            const float wv0 = wkm[k * 16 + wq];
            const float wv1 = wkm[k * 16 + wq + 1];
            s00 = fmaf(wv0, fx.x, s00); s01 = fmaf(wv0, fx.y, s01); s02 = fmaf(wv0, fx.z, s02);
            s10 = fmaf(wv1, fx.x, s10); s11 = fmaf(wv1, fx.y, s11); s12 = fmaf(wv1, fx.z, s12);
        }
        *(float4*)&agg_s[m * AGG_STRIDE + wq * CP + 64]       = make_float4(s00, s01, s02, 0.f);
        *(float4*)&agg_s[m * AGG_STRIDE + (wq + 1) * CP + 64] = make_float4(s10, s11, s12, 0.f);
    }
    __syncthreads();

    // ---------------- Phase 3: final GEMM out = leaky(agg @ linw^T + b) ---------------
    {
        const int mg = tid & 7;        // 8 lane groups; thread's points m = mg + 8*i
        const int og = tid >> 3;       // 32 output groups of 4
        float acc[4][4];
        #pragma unroll
        for (int i = 0; i < 4; i++)
            #pragma unroll
            for (int r = 0; r < 4; r++) acc[i][r] = 0.f;

        #pragma unroll 2
        for (int j = 0; j < JTOT; j += 4) {
            float4 a[4];
            #pragma unroll
            for (int i = 0; i < 4; i++)
                a[i] = *(const float4*)&agg_s[(mg + 8 * i) * AGG_STRIDE + j];
            float4 wv[4];
            #pragma unroll
            for (int r = 0; r < 4; r++)
                wv[r] = *(const float4*)&g_linw[(og * 4 + r) * JTOT + j];
            #pragma unroll
            for (int i = 0; i < 4; i++) {
                #pragma unroll
                for (int r = 0; r < 4; r++) {
                    acc[i][r] = fmaf(a[i].x, wv[r].x, acc[i][r]);
                    acc[i][r] = fmaf(a[i].y, wv[r].y, acc[i][r]);
                    acc[i][r] = fmaf(a[i].z, wv[r].z, acc[i][r]);
                    acc[i][r] = fmaf(a[i].w, wv[r].w, acc[i][r]);
                }
            }
        }

        #pragma unroll
        for (int i = 0; i < 4; i++) {
            const int n = n0 + mg + 8 * i;
            #pragma unroll
            for (int r = 0; r < 4; r++) {
                const int o = og * 4 + r;
                out[(b * COUT + o) * N_ + n] = leaky(acc[i][r] + lin_b[o]);
            }
        }
    }
}

// ---------------------------------------------------------------------------
extern "C" void kernel_launch(void* const* d_in, const int* in_sizes, int n_in,
                              void* d_out, int out_size)
{
    const float* xyz  = (const float*)d_in[0];
    const float* feat = (const float*)d_in[1];
    const int*   knn  = (const int*)d_in[2];
    const float* w1   = (const float*)d_in[3];
    const float* b1   = (const float*)d_in[4];
    const float* w2   = (const float*)d_in[5];
    const float* b2   = (const float*)d_in[6];
    const float* lw   = (const float*)d_in[7];
    const float* lb   = (const float*)d_in[8];
    float* out = (float*)d_out;

    const int smem_bytes = (MT * AGG_STRIDE + MT * KNN * 16) * (int)sizeof(float)
                         + MT * KNN * (int)sizeof(int);   // 174,592 B

    cudaFuncSetAttribute(pointconv_main, cudaFuncAttributeMaxDynamicSharedMemorySize, smem_bytes);

    pack_linw<<<(COUT * JTOT + 255) / 256, 256>>>(lw);

    dim3 gp((N_ + 255) / 256, B_ * CP);
    pack_feats<<<gp, 256>>>(xyz, feat);

    pointconv_main<<<(B_ * N_) / MT, 256, smem_bytes>>>(xyz, knn, w1, b1, w2, b2, lb, out);
}

// round 5
// speedup vs baseline: 1.0115x; 1.0115x over previous
#include <cuda_runtime.h>

// Problem constants (fixed shapes)
#define B_    4
#define N_    16384
#define KNN   16
#define CIN   64
#define CP    68            // padded channels per row: [features 0..63, xyz 64..66, pad 67]
#define W16   16
#define JTOT  (W16 * CP)    // 1088
#define COUT  128
#define MT    32            // points per block in main kernel
#define AGG_STRIDE 1092     // smem row stride (multiple of 4; %32 == 4 -> conflict-free phase 3)
#define NEG_SLOPE 0.1f

// Scratch (static device globals; no runtime allocation)
__device__ __align__(16) float g_feats[B_ * N_ * CP];     // ~17.8 MB channel-last padded features
__device__ __align__(16) float g_linw[COUT * JTOT];       // ~557 KB re-laid-out lin_w

__device__ __forceinline__ float leaky(float x) { return x >= 0.f ? x : NEG_SLOPE * x; }

// ---- packed f32x2 helpers (Blackwell FFMA2: 2 fp32 FMA per instruction) ----
typedef unsigned long long u64;

__device__ __forceinline__ u64 fma2(u64 a, u64 b, u64 c) {
    u64 d;
    asm("fma.rn.f32x2 %0, %1, %2, %3;" : "=l"(d) : "l"(a), "l"(b), "l"(c));
    return d;
}
__device__ __forceinline__ u64 pack2(float x, float y) {
    u64 d;
    asm("mov.b64 %0, {%1, %2};" : "=l"(d) : "f"(x), "f"(y));
    return d;
}
__device__ __forceinline__ float2 unpack2(u64 v) {
    float2 r;
    asm("mov.b64 {%0, %1}, %2;" : "=f"(r.x), "=f"(r.y) : "l"(v));
    return r;
}

// ---------------------------------------------------------------------------
// Kernel 0a: repack lin_w [128, 16*67] -> [128, 16*68] with channel reorder
// ---------------------------------------------------------------------------
__global__ void pack_linw(const float* __restrict__ lin_w) {
    int idx = blockIdx.x * blockDim.x + threadIdx.x;
    if (idx >= COUT * JTOT) return;
    int o = idx / JTOT;
    int jj = idx % JTOT;
    int w = jj / CP;
    int c = jj % CP;
    float v = 0.f;
    if (c < 64)       v = lin_w[o * 1072 + w * 67 + (c + 3)];   // feature channel
    else if (c < 67)  v = lin_w[o * 1072 + w * 67 + (c - 64)];  // xyz channel
    g_linw[o * JTOT + jj] = v;
}

// ---------------------------------------------------------------------------
// Kernel 0b: build channel-last padded feats rows g_feats[(b*N + n)*68 + c]
// ---------------------------------------------------------------------------
__global__ void pack_feats(const float* __restrict__ xyz, const float* __restrict__ feat) {
    int n = blockIdx.x * blockDim.x + threadIdx.x;
    int bc = blockIdx.y;              // b*CP + c
    int b = bc / CP;
    int c = bc % CP;
    if (n >= N_) return;
    float v = 0.f;
    if (c < 64)       v = feat[(b * CIN + c) * N_ + n];
    else if (c < 67)  v = xyz[(b * 3 + (c - 64)) * N_ + n];
    g_feats[(b * N_ + n) * CP + c] = v;
}

// ---------------------------------------------------------------------------
// Main fused kernel: one block = 32 points.
// ---------------------------------------------------------------------------
extern __shared__ float s_mem[];

__global__ __launch_bounds__(256, 1)
void pointconv_main(const float* __restrict__ xyz, const int* __restrict__ knn,
                    const float* __restrict__ w1, const float* __restrict__ b1,
                    const float* __restrict__ w2, const float* __restrict__ b2,
                    const float* __restrict__ lin_b, float* __restrict__ out)
{
    float* agg_s = s_mem;                              // MT * AGG_STRIDE floats
    float* wk_s  = agg_s + MT * AGG_STRIDE;            // MT * KNN * 16 floats
    int*   gid_s = (int*)(wk_s + MT * KNN * 16);       // MT * KNN ints

    const int tid = threadIdx.x;
    const int p0  = blockIdx.x * MT;
    const int b   = p0 / N_;
    const int n0  = p0 % N_;

    // ---------------- Phase 1: neighbor-offset MLP (2 (m,k) pairs per thread) --------
    {
        const int m  = tid >> 3;               // 0..31
        const int k2 = (tid & 7) << 1;         // 0,2,...,14
        const int n  = n0 + m;
        const float cx0 = xyz[(b * 3 + 0) * N_ + n];
        const float cx1 = xyz[(b * 3 + 1) * N_ + n];
        const float cx2 = xyz[(b * 3 + 2) * N_ + n];
        #pragma unroll
        for (int kk = 0; kk < 2; kk++) {
            const int k = k2 + kk;
            const int idx = knn[(b * N_ + n) * KNN + k];
            gid_s[m * KNN + k] = (b * N_ + idx) * CP;
            const float d0 = xyz[(b * 3 + 0) * N_ + idx] - cx0;
            const float d1 = xyz[(b * 3 + 1) * N_ + idx] - cx1;
            const float d2 = xyz[(b * 3 + 2) * N_ + idx] - cx2;
            float h[8];
            #pragma unroll
            for (int o = 0; o < 8; o++) {
                float s = fmaf(w1[o * 3 + 0], d0,
                          fmaf(w1[o * 3 + 1], d1,
                          fmaf(w1[o * 3 + 2], d2, b1[o])));
                h[o] = leaky(s);
            }
            #pragma unroll
            for (int o = 0; o < 16; o++) {
                float s = b2[o];
                #pragma unroll
                for (int hh = 0; hh < 8; hh++) s = fmaf(w2[o * 8 + hh], h[hh], s);
                wk_s[(m * KNN + k) * 16 + o] = leaky(s);
            }
        }
    }
    __syncthreads();

    // ---------------- Phase 2: agg accumulation (packed f32x2) ------------------------
    {
        const int m  = tid >> 3;               // 0..31 (point)
        const int cb = (tid & 7) << 3;         // feature-channel base, 0..56 step 8
        const int*   gidx = &gid_s[m * KNN];
        const float* wkm  = &wk_s[m * KNN * 16];

        // features part (c = 0..63): acc pairs along c; two halves of w (8 each)
        #pragma unroll
        for (int wp = 0; wp < 2; wp++) {
            u64 acc2[8][4];
            #pragma unroll
            for (int w = 0; w < 8; w++)
                #pragma unroll
                for (int cq = 0; cq < 4; cq++) acc2[w][cq] = 0ULL;

            #pragma unroll
            for (int k = 0; k < KNN; k++) {
                const float* f = &g_feats[gidx[k] + cb];
                const ulonglong2 fa = *(const ulonglong2*)f;        // c0c1, c2c3
                const ulonglong2 fb = *(const ulonglong2*)(f + 4);  // c4c5, c6c7
                const u64 fv[4] = {fa.x, fa.y, fb.x, fb.y};
                const float4 wv0 = *(const float4*)&wkm[k * 16 + wp * 8];
                const float4 wv1 = *(const float4*)&wkm[k * 16 + wp * 8 + 4];
                const u64 wv2[8] = {
                    pack2(wv0.x, wv0.x), pack2(wv0.y, wv0.y),
                    pack2(wv0.z, wv0.z), pack2(wv0.w, wv0.w),
                    pack2(wv1.x, wv1.x), pack2(wv1.y, wv1.y),
                    pack2(wv1.z, wv1.z), pack2(wv1.w, wv1.w)};
                #pragma unroll
                for (int w = 0; w < 8; w++)
                    #pragma unroll
                    for (int cq = 0; cq < 4; cq++)
                        acc2[w][cq] = fma2(wv2[w], fv[cq], acc2[w][cq]);
            }
            #pragma unroll
            for (int w = 0; w < 8; w++) {
                u64* dst = (u64*)&agg_s[m * AGG_STRIDE + (wp * 8 + w) * CP + cb];
                ((ulonglong2*)dst)[0] = make_ulonglong2(acc2[w][0], acc2[w][1]);
                ((ulonglong2*)dst)[1] = make_ulonglong2(acc2[w][2], acc2[w][3]);
            }
        }

        // xyz part (c = 64..66, pad 67=0); each thread handles 2 w's
        const int wq = (tid & 7) << 1;
        float s00 = 0.f, s01 = 0.f, s02 = 0.f;
        float s10 = 0.f, s11 = 0.f, s12 = 0.f;
        #pragma unroll
        for (int k = 0; k < KNN; k++) {
            const int g = gidx[k];
            const float4 fx = *(const float4*)&g_feats[g + 64];   // x, y, z, 0
            const float wv0 = wkm[k * 16 + wq];
            const float wv1 = wkm[k * 16 + wq + 1];
            s00 = fmaf(wv0, fx.x, s00); s01 = fmaf(wv0, fx.y, s01); s02 = fmaf(wv0, fx.z, s02);
            s10 = fmaf(wv1, fx.x, s10); s11 = fmaf(wv1, fx.y, s11); s12 = fmaf(wv1, fx.z, s12);
        }
        *(float4*)&agg_s[m * AGG_STRIDE + wq * CP + 64]       = make_float4(s00, s01, s02, 0.f);
        *(float4*)&agg_s[m * AGG_STRIDE + (wq + 1) * CP + 64] = make_float4(s10, s11, s12, 0.f);
    }
    __syncthreads();

    // ---------------- Phase 3: final GEMM (packed f32x2, pairs along j) ---------------
    {
        const int mg = tid & 7;        // 8 lane groups; thread's points m = mg + 8*i
        const int og = tid >> 3;       // 32 output groups of 4
        u64 acc2[4][4][2];
        #pragma unroll
        for (int i = 0; i < 4; i++)
            #pragma unroll
            for (int r = 0; r < 4; r++) { acc2[i][r][0] = 0ULL; acc2[i][r][1] = 0ULL; }

        #pragma unroll 2
        for (int j = 0; j < JTOT; j += 4) {
            ulonglong2 a2[4];
            #pragma unroll
            for (int i = 0; i < 4; i++)
                a2[i] = *(const ulonglong2*)&agg_s[(mg + 8 * i) * AGG_STRIDE + j];
            ulonglong2 w2[4];
            #pragma unroll
            for (int r = 0; r < 4; r++)
                w2[r] = *(const ulonglong2*)&g_linw[(og * 4 + r) * JTOT + j];
            #pragma unroll
            for (int i = 0; i < 4; i++) {
                #pragma unroll
                for (int r = 0; r < 4; r++) {
                    acc2[i][r][0] = fma2(a2[i].x, w2[r].x, acc2[i][r][0]);
                    acc2[i][r][1] = fma2(a2[i].y, w2[r].y, acc2[i][r][1]);
                }
            }
        }

        #pragma unroll
        for (int i = 0; i < 4; i++) {
            const int n = n0 + mg + 8 * i;
            #pragma unroll
            for (int r = 0; r < 4; r++) {
                const int o = og * 4 + r;
                const float2 p0 = unpack2(acc2[i][r][0]);
                const float2 p1 = unpack2(acc2[i][r][1]);
                const float s = (p0.x + p0.y) + (p1.x + p1.y);
                out[(b * COUT + o) * N_ + n] = leaky(s + lin_b[o]);
            }
        }
    }
}

// ---------------------------------------------------------------------------
extern "C" void kernel_launch(void* const* d_in, const int* in_sizes, int n_in,
                              void* d_out, int out_size)
{
    const float* xyz  = (const float*)d_in[0];
    const float* feat = (const float*)d_in[1];
    const int*   knn  = (const int*)d_in[2];
    const float* w1   = (const float*)d_in[3];
    const float* b1   = (const float*)d_in[4];
    const float* w2   = (const float*)d_in[5];
    const float* b2   = (const float*)d_in[6];
    const float* lw   = (const float*)d_in[7];
    const float* lb   = (const float*)d_in[8];
    float* out = (float*)d_out;

    const int smem_bytes = (MT * AGG_STRIDE + MT * KNN * 16) * (int)sizeof(float)
                         + MT * KNN * (int)sizeof(int);   // 174,592 B

    cudaFuncSetAttribute(pointconv_main, cudaFuncAttributeMaxDynamicSharedMemorySize, smem_bytes);

    pack_linw<<<(COUT * JTOT + 255) / 256, 256>>>(lw);

    dim3 gp((N_ + 255) / 256, B_ * CP);
    pack_feats<<<gp, 256>>>(xyz, feat);

    pointconv_main<<<(B_ * N_) / MT, 256, smem_bytes>>>(xyz, knn, w1, b1, w2, b2, lb, out);
}

// round 7
// speedup vs baseline: 1.7244x; 1.7048x over previous
#include <cuda_runtime.h>
#include <cuda_bf16.h>

typedef unsigned int       u32;
typedef unsigned long long u64;

// Problem constants
#define B_     4
#define N_     16384
#define KNN    16
#define CIN    64
#define CP     68
#define JTOT   1088           // j' = c*16 + w
#define NCHUNK 17             // 17 chunks of 64 j'
#define COUT   128
#define MT     128            // points per block
#define NEG_SLOPE 0.1f
#define WK_STRIDE 260

// smem byte offsets (A/W tiles 1024-aligned for the 128B swizzle)
#define A_HI_OFF   0                            // 128x64 bf16 = 16384 B
#define A_LO_OFF   16384
#define W_HI_OFF   32768
#define W_LO_OFF   49152
#define WK_OFF     65536                        // float[128][260] = 133120 B
#define GID_OFF    (WK_OFF + 133120)            // int[128*16] = 8192 B
#define SMEM_TOTAL (GID_OFF + 8192)             // 206848 B

#define STAGE_STRIDE 132                        // epilogue f32 stage stride

// Static device scratch
__device__ __align__(16) float          g_feats[B_ * N_ * CP];
__device__ __align__(16) __nv_bfloat16  g_w_hi[NCHUNK * 128 * 64];   // pre-swizzled tiles
__device__ __align__(16) __nv_bfloat16  g_w_lo[NCHUNK * 128 * 64];

__device__ __forceinline__ float leaky(float x) { return x >= 0.f ? x : NEG_SLOPE * x; }

// ---- helpers ----------------------------------------------------------------
__device__ __forceinline__ u32 s2u(const void* p) {
    u32 a;
    asm("{ .reg .u64 t; cvta.to.shared.u64 t, %1; cvt.u32.u64 %0, t; }" : "=r"(a) : "l"(p));
    return a;
}
__device__ __forceinline__ u64 fma2(u64 a, u64 b, u64 c) {
    u64 d; asm("fma.rn.f32x2 %0, %1, %2, %3;" : "=l"(d) : "l"(a), "l"(b), "l"(c)); return d;
}
__device__ __forceinline__ u64 pack2(float x, float y) {
    u64 d; asm("mov.b64 %0, {%1, %2};" : "=l"(d) : "f"(x), "f"(y)); return d;
}
__device__ __forceinline__ float2 unpack2(u64 v) {
    float2 r; asm("mov.b64 {%0, %1}, %2;" : "=f"(r.x), "=f"(r.y) : "l"(v)); return r;
}
__device__ __forceinline__ u32 sw128(u32 off) { return off ^ ((off >> 3) & 0x70); }

__device__ __forceinline__ void ldsm4(u32* r, u32 addr) {
    asm volatile("ldmatrix.sync.aligned.m8n8.x4.shared.b16 {%0,%1,%2,%3}, [%4];"
                 : "=r"(r[0]), "=r"(r[1]), "=r"(r[2]), "=r"(r[3]) : "r"(addr));
}
__device__ __forceinline__ void mma_bf16(float* c, const u32* a, u32 b0, u32 b1) {
    asm volatile("mma.sync.aligned.m16n8k16.row.col.f32.bf16.bf16.f32 "
                 "{%0,%1,%2,%3}, {%4,%5,%6,%7}, {%8,%9}, {%0,%1,%2,%3};"
                 : "+f"(c[0]), "+f"(c[1]), "+f"(c[2]), "+f"(c[3])
                 : "r"(a[0]), "r"(a[1]), "r"(a[2]), "r"(a[3]), "r"(b0), "r"(b1));
}

// ---------------------------------------------------------------------------
// pack_w: lin_w [128, 16*67] -> hi/lo bf16 tiles, j' = c*16+w, pre-swizzled.
// ---------------------------------------------------------------------------
__global__ void pack_w(const float* __restrict__ lin_w) {
    int idx = blockIdx.x * blockDim.x + threadIdx.x;
    if (idx >= COUT * JTOT) return;
    int o = idx / JTOT;
    int jp = idx % JTOT;
    int w = jp & 15;
    int c = jp >> 4;
    float v = 0.f;
    if (c < 64)      v = lin_w[o * 1072 + w * 67 + (c + 3)];
    else if (c < 67) v = lin_w[o * 1072 + w * 67 + (c - 64)];
    __nv_bfloat16 hi = __float2bfloat16(v);
    __nv_bfloat16 lo = __float2bfloat16(v - __bfloat162float(hi));
    int q  = jp >> 6;
    int jl = jp & 63;
    u32 off = (u32)(o * 128 + jl * 2);
    u32 pos = sw128(off) >> 1;
    g_w_hi[q * 8192 + pos] = hi;
    g_w_lo[q * 8192 + pos] = lo;
}

// ---------------------------------------------------------------------------
// pack_feats: channel-last padded rows g_feats[(b*N+n)*68 + c]
// ---------------------------------------------------------------------------
__global__ void pack_feats(const float* __restrict__ xyz, const float* __restrict__ feat) {
    int n = blockIdx.x * blockDim.x + threadIdx.x;
    int bc = blockIdx.y;
    int b = bc / CP;
    int c = bc % CP;
    if (n >= N_) return;
    float v = 0.f;
    if (c < 64)      v = feat[(b * CIN + c) * N_ + n];
    else if (c < 67) v = xyz[(b * 3 + (c - 64)) * N_ + n];
    g_feats[(b * N_ + n) * CP + c] = v;
}

// ---------------------------------------------------------------------------
// Main kernel: 128 points/block, 256 threads, ldmatrix + mma.sync bf16 hi/lo.
// ---------------------------------------------------------------------------
extern __shared__ char s_raw[];

__global__ __launch_bounds__(256, 1)
void pointconv_main(const float* __restrict__ xyz, const int* __restrict__ knn,
                    const float* __restrict__ w1, const float* __restrict__ b1,
                    const float* __restrict__ w2, const float* __restrict__ b2,
                    const float* __restrict__ lin_b, float* __restrict__ out)
{
    const u32 sbase = s2u(s_raw);
    float* wk_s  = (float*)(s_raw + WK_OFF);
    int*   gid_s = (int*)(s_raw + GID_OFF);

    const int tid = threadIdx.x;
    const int wid = tid >> 5;
    const int lid = tid & 31;
    const int p0  = blockIdx.x * MT;
    const int b   = p0 / N_;
    const int n0  = p0 % N_;

    // ---------------- Phase 1: weight MLP, 8 (m,k) pairs per thread ------------------
    {
        const int m  = tid >> 1;
        const int kh = (tid & 1) * 8;
        const int n  = n0 + m;
        const float cx0 = xyz[(b * 3 + 0) * N_ + n];
        const float cx1 = xyz[(b * 3 + 1) * N_ + n];
        const float cx2 = xyz[(b * 3 + 2) * N_ + n];
        #pragma unroll
        for (int kk = 0; kk < 8; kk++) {
            const int k = kh + kk;
            const int idx = knn[(b * N_ + n) * KNN + k];
            gid_s[m * KNN + k] = (b * N_ + idx) * CP;
            const float d0 = xyz[(b * 3 + 0) * N_ + idx] - cx0;
            const float d1 = xyz[(b * 3 + 1) * N_ + idx] - cx1;
            const float d2 = xyz[(b * 3 + 2) * N_ + idx] - cx2;
            float h[8];
            #pragma unroll
            for (int o = 0; o < 8; o++) {
                float s = fmaf(w1[o * 3 + 0], d0,
                          fmaf(w1[o * 3 + 1], d1,
                          fmaf(w1[o * 3 + 2], d2, b1[o])));
                h[o] = leaky(s);
            }
            float wv[16];
            #pragma unroll
            for (int o = 0; o < 16; o++) {
                float s = b2[o];
                #pragma unroll
                for (int hh = 0; hh < 8; hh++) s = fmaf(w2[o * 8 + hh], h[hh], s);
                wv[o] = leaky(s);
            }
            float* dst = &wk_s[m * WK_STRIDE + k * 16];
            *(float4*)(dst)      = make_float4(wv[0],  wv[1],  wv[2],  wv[3]);
            *(float4*)(dst + 4)  = make_float4(wv[4],  wv[5],  wv[6],  wv[7]);
            *(float4*)(dst + 8)  = make_float4(wv[8],  wv[9],  wv[10], wv[11]);
            *(float4*)(dst + 12) = make_float4(wv[12], wv[13], wv[14], wv[15]);
        }
    }
    __syncthreads();

    // per-thread phase-2 roles: one point m, one w-half
    const int m  = tid >> 1;
    const int wh = tid & 1;                  // w in [wh*8, wh*8+8)
    const int*   gidx = &gid_s[m * KNN];
    const float* wkm  = &wk_s[m * WK_STRIDE + wh * 8];

    // per-warp MMA tiling: 4 (m) x 2 (n) warps, each 32m x 64n
    const int wm = wid & 3;
    const int wn = wid >> 2;

    float accf[2][8][4];                     // [mtile][ntile][frag]
    #pragma unroll
    for (int t = 0; t < 2; t++)
        #pragma unroll
        for (int nt = 0; nt < 8; nt++)
            #pragma unroll
            for (int r = 0; r < 4; r++) accf[t][nt][r] = 0.f;

    // precompute lane-dependent ldmatrix address components
    const u32 a_row = (u32)((lid & 7) + ((lid >> 3) & 1) * 8);   // row within m16
    const u32 a_kb  = (u32)(((lid >> 4) & 1) * 16);              // k-byte within k-step
    const u32 b_row = (u32)((lid & 7) + ((lid >> 4) & 1) * 8);   // row within n16
    const u32 b_kb  = (u32)(((lid >> 3) & 1) * 16);

    for (int q = 0; q < NCHUNK; q++) {
        // prefetch W tiles (pre-swizzled) into regs
        uint4 wreg[8];
        {
            const uint4* srch = (const uint4*)g_w_hi + q * 1024;
            const uint4* srcl = (const uint4*)g_w_lo + q * 1024;
            #pragma unroll
            for (int i = 0; i < 4; i++) {
                wreg[i]     = srch[tid + i * 256];
                wreg[4 + i] = srcl[tid + i * 256];
            }
        }

        // ---- phase 2: A slice (4 c x 8 w per thread), fp32x2 ----
        u64 acc2[4][4];                      // [c][w-pair]
        #pragma unroll
        for (int c = 0; c < 4; c++)
            #pragma unroll
            for (int p = 0; p < 4; p++) acc2[c][p] = 0ULL;

        const int cb = 4 * q;
        #pragma unroll
        for (int k = 0; k < KNN; k++) {
            const float4 f = *(const float4*)&g_feats[gidx[k] + cb];
            const ulonglong2 wa = *(const ulonglong2*)&wkm[k * 16];
            const ulonglong2 wb = *(const ulonglong2*)&wkm[k * 16 + 4];
            const u64 wp4[4] = {wa.x, wa.y, wb.x, wb.y};
            const u64 fc[4] = {pack2(f.x, f.x), pack2(f.y, f.y),
                               pack2(f.z, f.z), pack2(f.w, f.w)};
            #pragma unroll
            for (int c = 0; c < 4; c++)
                #pragma unroll
                for (int p = 0; p < 4; p++)
                    acc2[c][p] = fma2(wp4[p], fc[c], acc2[c][p]);
        }

        // ---- split to bf16 hi/lo, store swizzled into A tiles ----
        #pragma unroll
        for (int c = 0; c < 4; c++) {
            u32 hw[4], lw[4];
            #pragma unroll
            for (int p = 0; p < 4; p++) {
                const float2 f2 = unpack2(acc2[c][p]);
                __nv_bfloat162 h2 = __floats2bfloat162_rn(f2.x, f2.y);
                const float rx = f2.x - __bfloat162float(h2.x);
                const float ry = f2.y - __bfloat162float(h2.y);
                __nv_bfloat162 l2 = __floats2bfloat162_rn(rx, ry);
                hw[p] = *(u32*)&h2;
                lw[p] = *(u32*)&l2;
            }
            const u32 off = sw128((u32)(m * 128 + c * 32 + wh * 16));
            *(uint4*)(s_raw + A_HI_OFF + off) = make_uint4(hw[0], hw[1], hw[2], hw[3]);
            *(uint4*)(s_raw + A_LO_OFF + off) = make_uint4(lw[0], lw[1], lw[2], lw[3]);
        }
        // store W tiles (already swizzled)
        {
            uint4* dsth = (uint4*)(s_raw + W_HI_OFF);
            uint4* dstl = (uint4*)(s_raw + W_LO_OFF);
            #pragma unroll
            for (int i = 0; i < 4; i++) {
                dsth[tid + i * 256] = wreg[i];
                dstl[tid + i * 256] = wreg[4 + i];
            }
        }
        __syncthreads();

        // ---- MMA: 4 k-steps x (2 mtiles x 8 ntiles x 3 splits) ----
        #pragma unroll
        for (int ks = 0; ks < 4; ks++) {
            u32 ah[2][4], al[2][4];
            #pragma unroll
            for (int t = 0; t < 2; t++) {
                const u32 mr = (u32)(wm * 32 + t * 16) + a_row;
                const u32 o_sw = sw128(mr * 128 + (u32)(ks * 32) + a_kb);
                ldsm4(ah[t], sbase + A_HI_OFF + o_sw);
                ldsm4(al[t], sbase + A_LO_OFF + o_sw);
            }
            #pragma unroll
            for (int ng = 0; ng < 4; ng++) {
                const u32 orow = (u32)(wn * 64 + ng * 16) + b_row;
                const u32 o_sw = sw128(orow * 128 + (u32)(ks * 32) + b_kb);
                u32 bh[4], bl[4];
                ldsm4(bh, sbase + W_HI_OFF + o_sw);
                ldsm4(bl, sbase + W_LO_OFF + o_sw);
                #pragma unroll
                for (int t = 0; t < 2; t++) {
                    float* c0 = accf[t][ng * 2];
                    float* c1 = accf[t][ng * 2 + 1];
                    mma_bf16(c0, ah[t], bh[0], bh[1]);
                    mma_bf16(c0, ah[t], bl[0], bl[1]);
                    mma_bf16(c0, al[t], bh[0], bh[1]);
                    mma_bf16(c1, ah[t], bh[2], bh[3]);
                    mma_bf16(c1, ah[t], bl[2], bl[3]);
                    mma_bf16(c1, al[t], bh[2], bh[3]);
                }
            }
        }
        __syncthreads();
    }

    // ---------------- Epilogue: stage via smem, coalesced store ----------------------
    float* stage = wk_s;     // reuse (wk no longer needed)
    {
        const int qr = lid >> 2;            // row within m16
        const int qc = 2 * (lid & 3);       // col within n8
        #pragma unroll
        for (int t = 0; t < 2; t++) {
            const int mr = wm * 32 + t * 16 + qr;
            #pragma unroll
            for (int nt = 0; nt < 8; nt++) {
                const int oc = wn * 64 + nt * 8 + qc;
                *(float2*)&stage[mr * STAGE_STRIDE + oc] =
                    make_float2(accf[t][nt][0], accf[t][nt][1]);
                *(float2*)&stage[(mr + 8) * STAGE_STRIDE + oc] =
                    make_float2(accf[t][nt][2], accf[t][nt][3]);
            }
        }
    }
    __syncthreads();
    {
        #pragma unroll
        for (int ow = 0; ow < 16; ow++) {
            const int o = wid * 16 + ow;
            const float bias = lin_b[o];
            float* orow = &out[(b * COUT + o) * N_ + n0];
            #pragma unroll
            for (int i = 0; i < 4; i++) {
                const int mm = lid + 32 * i;
                orow[mm] = leaky(stage[mm * STAGE_STRIDE + o] + bias);
            }
        }
    }
}

// ---------------------------------------------------------------------------
extern "C" void kernel_launch(void* const* d_in, const int* in_sizes, int n_in,
                              void* d_out, int out_size)
{
    const float* xyz  = (const float*)d_in[0];
    const float* feat = (const float*)d_in[1];
    const int*   knn  = (const int*)d_in[2];
    const float* w1   = (const float*)d_in[3];
    const float* b1   = (const float*)d_in[4];
    const float* w2   = (const float*)d_in[5];
    const float* b2   = (const float*)d_in[6];
    const float* lw   = (const float*)d_in[7];
    const float* lb   = (const float*)d_in[8];
    float* out = (float*)d_out;

    cudaFuncSetAttribute(pointconv_main, cudaFuncAttributeMaxDynamicSharedMemorySize, SMEM_TOTAL);

    pack_w<<<(COUT * JTOT + 255) / 256, 256>>>(lw);

    dim3 gp((N_ + 255) / 256, B_ * CP);
    pack_feats<<<gp, 256>>>(xyz, feat);

    pointconv_main<<<(B_ * N_) / MT, 256, SMEM_TOTAL>>>(xyz, knn, w1, b1, w2, b2, lb, out);
}